// round 1
// baseline (speedup 1.0000x reference)
#include <cuda_runtime.h>

#define N_NODES 10000
#define IN_CH   128
#define OUT_CH  64
#define NSTEP   16
#define E_EDGES 320000
#define K_SEL   (E_EDGES/2)
#define NB      16          // nodes per block in the node kernel
#define TIE_CAP 65536

// ---------------- device scratch (static, no allocation) ----------------
__device__ float        g_beta[N_NODES*NSTEP];     // beta per node per step
__device__ float        g_mean_beta[N_NODES];
__device__ float        g_val[N_NODES*OUT_CH];     // relu(x@Wv+bv)
__device__ unsigned int g_keys[E_EDGES];           // sortable score keys
__device__ unsigned char g_flags[E_EDGES];         // selected?
__device__ unsigned int g_mu[N_NODES*NSTEP];       // segment max (ordered-uint)
__device__ float        g_denom[N_NODES*NSTEP];
__device__ unsigned int g_hist[256];
__device__ unsigned int g_prefix;
__device__ int          g_kneed;
__device__ unsigned int g_thresh;
__device__ int          g_R;
__device__ int          g_tie_cnt;
__device__ int          g_tie_list[TIE_CAP];

// order-preserving float->uint (ascending)
__device__ __forceinline__ unsigned int fxform(float f) {
    unsigned int u = __float_as_uint(f);
    return (u & 0x80000000u) ? ~u : (u | 0x80000000u);
}
__device__ __forceinline__ float finv(unsigned int u) {
    return (u & 0x80000000u) ? __uint_as_float(u ^ 0x80000000u)
                             : __uint_as_float(~u);
}

// ---------------- init ----------------
__global__ void init_kernel(float* __restrict__ out) {
    int i = blockIdx.x * blockDim.x + threadIdx.x;
    int stride = gridDim.x * blockDim.x;
    for (int idx = i; idx < N_NODES*OUT_CH; idx += stride) out[idx] = 0.0f;
    for (int idx = i; idx < N_NODES*NSTEP; idx += stride) {
        g_mu[idx] = 0u;
        g_denom[idx] = 0.0f;
    }
    if (i < 256) g_hist[i] = 0u;
    if (i == 0) { g_prefix = 0u; g_kneed = K_SEL; g_tie_cnt = 0; }
}

// ---------------- per-node GEMMs + beta reduction ----------------
// block: 256 threads, NB=16 nodes.
// thread t owns W_inc columns t and t+256; threads 0..63 also own W_value col t.
__global__ __launch_bounds__(256) void node_kernel(
    const float* __restrict__ x,
    const float* __restrict__ p_t,
    const float* __restrict__ Wv, const float* __restrict__ bv,
    const float* __restrict__ Wi, const float* __restrict__ bi,
    const float* __restrict__ mw)
{
    __shared__ float xsT[IN_CH][NB];       // transposed x tile, 8KB
    __shared__ float hwS[NB][16][33];      // hw with per-step padding, ~33.8KB
    __shared__ float betaS[NB][17];

    int tid   = threadIdx.x;
    int node0 = blockIdx.x * NB;

    for (int idx = tid; idx < NB*IN_CH; idx += 256) {
        int n = idx >> 7, k = idx & 127;
        xsT[k][n] = x[(node0 + n)*IN_CH + k];
    }
    __syncthreads();

    float acc0[NB], acc1[NB], acc2[NB];
    #pragma unroll
    for (int n = 0; n < NB; n++) { acc0[n] = 0.f; acc1[n] = 0.f; acc2[n] = 0.f; }

    const bool has_v = (tid < 64);
    for (int k = 0; k < IN_CH; k++) {
        float w0 = Wi[k*512 + tid];
        float w1 = Wi[k*512 + tid + 256];
        float w2 = has_v ? Wv[k*64 + tid] : 0.0f;
        #pragma unroll
        for (int n = 0; n < NB; n++) {
            float xv = xsT[k][n];
            acc0[n] = fmaf(xv, w0, acc0[n]);
            acc1[n] = fmaf(xv, w1, acc1[n]);
            acc2[n] = fmaf(xv, w2, acc2[n]);
        }
    }

    // hw -> smem (with bias); layout hwS[n][j>>5][j&31]
    {
        int s0 = tid >> 5, k0 = tid & 31;
        float b0 = bi[tid], b1 = bi[tid + 256];
        #pragma unroll
        for (int n = 0; n < NB; n++) {
            hwS[n][s0][k0]     = acc0[n] + b0;
            hwS[n][s0 + 8][k0] = acc1[n] + b1;
        }
    }
    // value output (relu) straight to global
    if (has_v) {
        float bvv = bv[tid];
        #pragma unroll
        for (int n = 0; n < NB; n++) {
            float v = acc2[n] + bvv;
            g_val[(node0 + n)*64 + tid] = v > 0.f ? v : 0.f;
        }
    }
    __syncthreads();

    // beta[n][s] = (sum_k hw[n][s*32+k]*mw[n][k] + sum_k hw[n][s*32+16+k]*p_t[s][k]) / 32
    {
        int n = tid >> 4, s = tid & 15;
        const float* mwrow = mw + (node0 + n)*16;
        const float* ptrow = p_t + s*16;
        float sum = 0.f;
        #pragma unroll
        for (int k = 0; k < 16; k++) sum = fmaf(hwS[n][s][k],      mwrow[k], sum);
        #pragma unroll
        for (int k = 0; k < 16; k++) sum = fmaf(hwS[n][s][16 + k], ptrow[k], sum);
        float b = sum * (1.0f/32.0f);
        betaS[n][s] = b;
        g_beta[(node0 + n)*NSTEP + s] = b;
    }
    __syncthreads();
    if (tid < NB) {
        float s = 0.f;
        #pragma unroll
        for (int k = 0; k < NSTEP; k++) s += betaS[tid][k];
        g_mean_beta[node0 + tid] = s * (1.0f/NSTEP);
    }
}

// ---------------- edge score keys ----------------
__global__ void key_kernel(const int* __restrict__ ei, const float* __restrict__ ew) {
    int e = blockIdx.x * blockDim.x + threadIdx.x;
    if (e >= E_EDGES) return;
    int dst = ei[E_EDGES + e];
    float s = ew[e] * g_mean_beta[dst];
    s += 0.0f;                       // normalize -0 -> +0
    g_keys[e] = fxform(s);
}

// ---------------- radix select (top-K threshold), 4 passes ----------------
__global__ void hist_kernel(int pass) {
    __shared__ unsigned int h[256];
    if (threadIdx.x < 256) h[threadIdx.x] = 0u;
    __syncthreads();
    int shift = 24 - 8*pass;
    unsigned int pref = g_prefix;
    int i0 = blockIdx.x * blockDim.x + threadIdx.x;
    int stride = gridDim.x * blockDim.x;
    for (int e = i0; e < E_EDGES; e += stride) {
        unsigned int k = g_keys[e];
        unsigned int hi = (pass == 0) ? 0u : (k >> (shift + 8));
        if (pass == 0 || hi == pref)
            atomicAdd(&h[(k >> shift) & 255u], 1u);
    }
    __syncthreads();
    if (threadIdx.x < 256 && h[threadIdx.x])
        atomicAdd(&g_hist[threadIdx.x], h[threadIdx.x]);
}

__global__ void scan_kernel(int pass) {
    if (threadIdx.x == 0) {
        int kneed = g_kneed;
        unsigned int cum = 0;
        unsigned int pref = g_prefix;
        for (int b = 255; b >= 0; b--) {
            unsigned int c = g_hist[b];
            if (cum + c >= (unsigned int)kneed) {
                g_prefix = (pref << 8) | (unsigned int)b;
                g_kneed = kneed - (int)cum;
                break;
            }
            cum += c;
        }
        if (pass == 3) { g_thresh = g_prefix; g_R = g_kneed; }
    }
    __syncthreads();
    if (threadIdx.x < 256) g_hist[threadIdx.x] = 0u;
}

// ---------------- selection flags + tie handling ----------------
__global__ void flag_kernel() {
    int e = blockIdx.x * blockDim.x + threadIdx.x;
    if (e >= E_EDGES) return;
    unsigned int k = g_keys[e], t = g_thresh;
    unsigned char f = 0;
    if (k > t) f = 1;
    else if (k == t) {
        int p = atomicAdd(&g_tie_cnt, 1);
        if (p < TIE_CAP) g_tie_list[p] = e;
    }
    g_flags[e] = f;
}

__global__ void tie_kernel() {
    int T = g_tie_cnt; if (T > TIE_CAP) T = TIE_CAP;
    int R = g_R;
    for (int i = threadIdx.x; i < T; i += blockDim.x) {
        int idx = g_tie_list[i];
        int r = 0;
        for (int j = 0; j < T; j++) r += (g_tie_list[j] < idx);
        if (r < R) g_flags[idx] = 1;   // stable argsort: smallest indices win
    }
}

// ---------------- segment max over selected edges ----------------
__global__ void max_kernel(const int* __restrict__ ei, const float* __restrict__ ew) {
    int gid = blockIdx.x * blockDim.x + threadIdx.x;
    int e = gid >> 4;
    if (e >= E_EDGES || !g_flags[e]) return;
    int l = gid & 15;
    int src = ei[e], dst = ei[E_EDGES + e];
    float g = g_beta[dst*NSTEP + l] * ew[e];
    atomicMax(&g_mu[src*NSTEP + l], fxform(g));
}

// ---------------- exp + numerator/denominator accumulation ----------------
__global__ void acc_kernel(const int* __restrict__ ei, const float* __restrict__ ew,
                           float* __restrict__ out) {
    int gid = blockIdx.x * blockDim.x + threadIdx.x;
    int e = gid >> 4;
    if (e >= E_EDGES || !g_flags[e]) return;
    int l = gid & 15;
    int src = ei[e], dst = ei[E_EDGES + e];
    float g = g_beta[dst*NSTEP + l] * ew[e];
    float m = finv(g_mu[src*NSTEP + l]);
    float ex = expf(g - m);
    atomicAdd(&g_denom[src*NSTEP + l], ex);
    const float4 v = *reinterpret_cast<const float4*>(&g_val[dst*64 + l*4]);
    float* o = out + src*64 + l*4;
    atomicAdd(o + 0, v.x * ex);
    atomicAdd(o + 1, v.y * ex);
    atomicAdd(o + 2, v.z * ex);
    atomicAdd(o + 3, v.w * ex);
}

// ---------------- final divide ----------------
__global__ void fin_kernel(float* __restrict__ out) {
    int i = blockIdx.x * blockDim.x + threadIdx.x;
    if (i >= N_NODES*OUT_CH) return;
    int n = i >> 6;
    int s = (i >> 2) & 15;
    out[i] = out[i] / (g_denom[n*NSTEP + s] + 1e-16f);
}

// ---------------- launch ----------------
extern "C" void kernel_launch(void* const* d_in, const int* in_sizes, int n_in,
                              void* d_out, int out_size) {
    const float* x   = (const float*)d_in[0];
    const float* p_t = (const float*)d_in[1];
    const int*   ei  = (const int*)  d_in[2];
    const float* ew  = (const float*)d_in[3];
    const float* Wv  = (const float*)d_in[4];
    const float* bv  = (const float*)d_in[5];
    const float* Wi  = (const float*)d_in[6];
    const float* bi  = (const float*)d_in[7];
    const float* mw  = (const float*)d_in[8];
    float* out = (float*)d_out;

    init_kernel<<<640, 256>>>(out);
    node_kernel<<<N_NODES/NB, 256>>>(x, p_t, Wv, bv, Wi, bi, mw);
    key_kernel<<<(E_EDGES + 255)/256, 256>>>(ei, ew);
    for (int pass = 0; pass < 4; pass++) {
        hist_kernel<<<256, 256>>>(pass);
        scan_kernel<<<1, 256>>>(pass);
    }
    flag_kernel<<<(E_EDGES + 255)/256, 256>>>();
    tie_kernel<<<1, 256>>>();
    int eg = (E_EDGES*16 + 255)/256;
    max_kernel<<<eg, 256>>>(ei, ew);
    acc_kernel<<<eg, 256>>>(ei, ew, out);
    fin_kernel<<<(N_NODES*OUT_CH + 255)/256, 256>>>(out);
}